// round 11
// baseline (speedup 1.0000x reference)
#include <cuda_runtime.h>
#include <cuda_bf16.h>

#define B_ 8
#define H_ 12
#define N_ 577
#define HD_ 64
#define NNU  332929u           // N*N
#define SLAB (12u*NNU)         // one batch slab: 3,995,148 (divisible by 4)
#define SLAB4 (SLAB/4u)        // 998,787 float4 vectors
#define NROWS 6924u            // rows per slab (12*577)
#define LOG2E 1.4426950408889634f

#define BLK 512u
#define EPB 2048u                          // elements per block
#define NBLK ((SLAB4 + BLK - 1u)/BLK)      // 1951
#define ROWS_PB 5                          // max rows a 2048-elem window touches
#define NTOKPB (ROWS_PB*8)                 // 40 tokens per block
#define MLP_THREADS (NTOKPB*4)             // 160 (4 threads per token)

__device__ __forceinline__ float ex2a(float x){ float r; asm("ex2.approx.f32 %0,%1;" : "=f"(r) : "f"(x)); return r; }
__device__ __forceinline__ float rcpa(float x){ float r; asm("rcp.approx.f32 %0,%1;" : "=f"(r) : "f"(x)); return r; }

// mask = 1/(1+r^10), r = A*(1-u)/u, A = (1-p)/p = exp2(w'')-1 (Sterbenz-exact),
// clamped to the f32 image of the reference's clip(p, 1e-6, 1-1e-6).
// Row-max is provably 1.0 (PD quadratic form => w<=0; CLS col gives w=0 in
// every row), so no row reduction exists.
__device__ __forceinline__ float mask_lane(float uu, float xx, float xy, float yy,
                                           float4 c)
{
    float w = fmaf(c.x, xx, fmaf(c.y, xy, c.z * yy));   // >= 0
    float A = ex2a(w) - 1.0f;
    A = fminf(fmaxf(A, 1.0132800e-06f), 999999.0f);
    float r = A * (1.0f - uu) * rcpa(uu);
    float r2 = r * r;
    float r4 = r2 * r2;
    float r10 = r4 * r4 * r2;     // inf -> mask 0; 0 -> mask 1 (matches ref saturation)
    return rcpa(1.0f + r10);
}

// ---------------------------------------------------------------------------
// FUSED kernel: each block computes the <=40 token coefficients its own
// 2048-element window needs (prologue, 160 threads, 4 threads/token, h[16]),
// stores them in smem, then streams its window across all 8 batches.
// The MLP instructions fill the streaming phase's idle issue slots of the
// other resident blocks -> the separate 36us MLP kernel disappears.
// Per-lane coef indexing from smem also absorbs row-crossing vectors with a
// single uniform code path (no divergent warps, no tail blocks).
// ---------------------------------------------------------------------------
__global__ __launch_bounds__(512, 2) void fused_kernel(
    const float* __restrict__ q,
    const float* __restrict__ W1,
    const float* __restrict__ b1,
    const float* __restrict__ W2,
    const float* __restrict__ b2,
    const float* __restrict__ u,
    const float* __restrict__ dists,
    float* __restrict__ out)
{
    __shared__ float4 coefs[NTOKPB];        // [rel*8 + b]

    const unsigned tid = threadIdx.x;
    const unsigned bx  = blockIdx.x;
    const unsigned r0  = (bx * EPB) / 577u; // first row this block touches

    // ================= prologue: sigma MLP for this block's tokens ==========
    if (tid < MLP_THREADS) {
        const unsigned tok_i = tid >> 2;          // 0..39
        const unsigned qt    = tid & 3u;          // hidden-unit quarter
        const unsigned rel   = tok_i >> 3;        // 0..4 (row offset)
        const unsigned b     = tok_i & 7u;        // batch
        unsigned rowg = r0 + rel;
        if (rowg > NROWS - 1u) rowg = NROWS - 1u; // last-block clamp (dup compute)
        const unsigned token = b * NROWS + rowg;

        const float4* q4 = (const float4*)(q + (size_t)token * HD_);

        float h[16];
        #pragma unroll
        for (int j = 0; j < 16; j++) h[j] = __ldg(&b1[qt * 16u + j]);

        #pragma unroll 2
        for (int k4 = 0; k4 < 16; k4++) {
            const float4 qv = __ldg(&q4[k4]);
            const float qk[4] = {qv.x, qv.y, qv.z, qv.w};
            #pragma unroll
            for (int kk = 0; kk < 4; kk++) {
                const float qc = qk[kk];
                const float4* wrow = (const float4*)(W1 + (k4 * 4 + kk) * 64) + qt * 4u;
                #pragma unroll
                for (int j4 = 0; j4 < 4; j4++) {
                    const float4 w = __ldg(&wrow[j4]);
                    h[4*j4+0] = fmaf(qc, w.x, h[4*j4+0]);
                    h[4*j4+1] = fmaf(qc, w.y, h[4*j4+1]);
                    h[4*j4+2] = fmaf(qc, w.z, h[4*j4+2]);
                    h[4*j4+3] = fmaf(qc, w.w, h[4*j4+3]);
                }
            }
        }

        float s0 = 0.f, s1 = 0.f, s2 = 0.f;
        #pragma unroll
        for (int j = 0; j < 16; j++) {
            float x = h[j];
            float g = 0.5f * x * (1.0f + erff(x * 0.70710678118654752f));  // exact gelu
            const unsigned jg = (qt * 16u + j) * 3u;
            s0 = fmaf(g, __ldg(&W2[jg+0]), s0);
            s1 = fmaf(g, __ldg(&W2[jg+1]), s1);
            s2 = fmaf(g, __ldg(&W2[jg+2]), s2);
        }
        // reduce over the 4 threads of this token (lanes differ in bits 0..1)
        s0 += __shfl_xor_sync(0xffffffffu, s0, 1);
        s1 += __shfl_xor_sync(0xffffffffu, s1, 1);
        s2 += __shfl_xor_sync(0xffffffffu, s2, 1);
        s0 += __shfl_xor_sync(0xffffffffu, s0, 2);
        s1 += __shfl_xor_sync(0xffffffffu, s1, 2);
        s2 += __shfl_xor_sync(0xffffffffu, s2, 2);

        if (qt == 0) {
            s0 += __ldg(&b2[0]); s1 += __ldg(&b2[1]); s2 += __ldg(&b2[2]);
            float sx  = fmaxf(s0, 0.0f) + 1.0f;
            float sy  = fmaxf(s1, 0.0f) + 1.0f;
            float rho = 0.99f * tanhf(s2);
            float sxx = sx * sx;
            float syy = sy * sy;
            float sxy = rho * sx * sy;
            float det = sxx * syy - sxy * sxy;   // > 0 always (rho^2 < 0.9801)
            float rdet = 1.0f / det;
            // POSITIVE quadratic form pre-scaled by log2(e): p = exp2(-w'')
            coefs[tok_i] = make_float4( 0.5f * syy * rdet * LOG2E,
                                       -sxy * rdet * LOG2E,
                                        0.5f * sxx * rdet * LOG2E, 0.f);
        }
    }
    __syncthreads();

    // ================= streaming phase =====================================
    const unsigned v = bx * BLK + tid;
    if (v >= SLAB4) return;
    const unsigned e0 = v * 4u;

    const float2* __restrict__ d2 = (const float2*)dists;

    // per-lane geometry + smem coef index (loop-invariant over batches)
    float xxl[4], xyl[4], yyl[4];
    unsigned cidx[4];
    #pragma unroll
    for (int k = 0; k < 4; k++) {
        const unsigned ek = e0 + (unsigned)k;
        const unsigned rg = ek / 577u;            // global row 0..6923
        const unsigned jk = ek - rg * 577u;
        const unsigned ik = rg % 577u;
        cidx[k] = (rg - r0) * 8u;                 // rel*8
        const float2 d = d2[(size_t)ik * 577u + jk];
        xxl[k] = d.x * d.x;
        xyl[k] = d.x * d.y;
        yyl[k] = d.y * d.y;
    }

    #pragma unroll 2
    for (unsigned b = 0; b < 8; b++) {
        const size_t off = (size_t)e0 + (size_t)b * SLAB;
        const float4 u4 = __ldcs((const float4*)(u + off));
        float4 res;
        res.x = mask_lane(u4.x, xxl[0], xyl[0], yyl[0], coefs[cidx[0] + b]);
        res.y = mask_lane(u4.y, xxl[1], xyl[1], yyl[1], coefs[cidx[1] + b]);
        res.z = mask_lane(u4.z, xxl[2], xyl[2], yyl[2], coefs[cidx[2] + b]);
        res.w = mask_lane(u4.w, xxl[3], xyl[3], yyl[3], coefs[cidx[3] + b]);
        __stcs((float4*)(out + off), res);
    }
}

extern "C" void kernel_launch(void* const* d_in, const int* in_sizes, int n_in,
                              void* d_out, int out_size)
{
    const float* query = (const float*)d_in[0];
    const float* W1    = (const float*)d_in[1];
    const float* b1    = (const float*)d_in[2];
    const float* W2    = (const float*)d_in[3];
    const float* b2    = (const float*)d_in[4];
    const float* u     = (const float*)d_in[5];
    const float* dists = (const float*)d_in[6];
    float* out = (float*)d_out;

    fused_kernel<<<NBLK, BLK>>>(query, W1, b1, W2, b2, u, dists, out);
}

// round 12
// speedup vs baseline: 1.4588x; 1.4588x over previous
#include <cuda_runtime.h>
#include <cuda_bf16.h>

#define B_ 8
#define H_ 12
#define N_ 577
#define HD_ 64
#define BH_ (B_*H_)            // 96
#define NTOK (BH_*N_)          // 55392
#define NPAIR (NTOK/2)         // 27696
#define NNU  332929u           // N*N
#define SLAB (12u*NNU)         // one batch slab: 3,995,148 (divisible by 4)
#define SLAB4 (SLAB/4u)        // 998,787
#define NROWS (12u*577u)       // 6924 rows per slab
#define LOG2E 1.4426950408889634f

#define NB_MAIN ((SLAB4 + 255u)/256u)     // 3902
#define N_CROSS 5193u                      // boundaries 577m, m=1..6923, m%4!=0
#define NB_CROSS ((N_CROSS + 255u)/256u)  // 21

// Per-token coefficients, sign-flipped & pre-scaled by log2(e):
// w'' = c.x*dx^2 + c.y*dx*dy + c.z*dy^2  >= 0,  p = exp2(-w'')
__device__ float4 g_coef4[NTOK];

__device__ __forceinline__ float ex2a(float x){ float r; asm("ex2.approx.f32 %0,%1;" : "=f"(r) : "f"(x)); return r; }
__device__ __forceinline__ float rcpa(float x){ float r; asm("rcp.approx.f32 %0,%1;" : "=f"(r) : "f"(x)); return r; }

// ---------------------------------------------------------------------------
// Kernel 1: sigma MLP — quarter-split token pairs.
// Each thread: 16 hidden units x 2 consecutive tokens (h-regs = 32).
// 4 threads per token-pair, shfl_xor(1),(2) reduction.
// LDS.128 per thread = 256, each feeding 8 FMAs -> smem floor ~13us;
// regs ~56 -> launch_bounds(256,4) -> 32 warps/SM, grid 433 = one wave.
// ---------------------------------------------------------------------------
__global__ __launch_bounds__(256, 4) void mlp_kernel(
    const float* __restrict__ q,
    const float* __restrict__ W1,
    const float* __restrict__ b1,
    const float* __restrict__ W2,
    const float* __restrict__ b2)
{
    __shared__ float4 w1s[64 * 16];   // [k][j4]
    __shared__ float  b1s[64];
    __shared__ float  w2s[64 * 3];
    __shared__ float  b2s[3];

    const int tid = threadIdx.x;
    for (int idx = tid; idx < 1024; idx += 256) w1s[idx] = ((const float4*)W1)[idx];
    if (tid < 64)  b1s[tid] = b1[tid];
    if (tid < 192) w2s[tid] = W2[tid];
    if (tid < 3)   b2s[tid] = b2[tid];
    __syncthreads();

    int pair = blockIdx.x * 64 + (tid >> 2);
    if (pair >= NPAIR) pair = NPAIR - 1;        // duplicate write, same value: benign
    const int qt = tid & 3;                      // hidden-unit quarter

    const float4* q0 = (const float4*)(q + (size_t)(2 * pair) * HD_);
    const float4* q1 = q0 + 16;

    float h0[16], h1[16];
    #pragma unroll
    for (int j = 0; j < 16; j++) { float b = b1s[qt * 16 + j]; h0[j] = b; h1[j] = b; }

    const int jbase = qt * 4;                    // float4 offset into 16-wide row
    #pragma unroll 2
    for (int k4 = 0; k4 < 16; k4++) {
        float4 a0 = q0[k4];
        float4 a1 = q1[k4];
        float c0k[4] = {a0.x, a0.y, a0.z, a0.w};
        float c1k[4] = {a1.x, a1.y, a1.z, a1.w};
        #pragma unroll
        for (int kk = 0; kk < 4; kk++) {
            const float c0 = c0k[kk];
            const float c1 = c1k[kk];
            const int krow = (k4 * 4 + kk) * 16 + jbase;
            #pragma unroll
            for (int j4 = 0; j4 < 4; j4++) {
                float4 w = w1s[krow + j4];
                h0[4*j4+0] = fmaf(c0, w.x, h0[4*j4+0]);
                h0[4*j4+1] = fmaf(c0, w.y, h0[4*j4+1]);
                h0[4*j4+2] = fmaf(c0, w.z, h0[4*j4+2]);
                h0[4*j4+3] = fmaf(c0, w.w, h0[4*j4+3]);
                h1[4*j4+0] = fmaf(c1, w.x, h1[4*j4+0]);
                h1[4*j4+1] = fmaf(c1, w.y, h1[4*j4+1]);
                h1[4*j4+2] = fmaf(c1, w.z, h1[4*j4+2]);
                h1[4*j4+3] = fmaf(c1, w.w, h1[4*j4+3]);
            }
        }
    }

    float s00 = 0.f, s01 = 0.f, s02 = 0.f;
    float s10 = 0.f, s11 = 0.f, s12 = 0.f;
    #pragma unroll
    for (int j = 0; j < 16; j++) {
        const int jg = (qt * 16 + j) * 3;
        const float w0 = w2s[jg+0], w1w = w2s[jg+1], w2w = w2s[jg+2];
        float x0 = h0[j];
        float g0 = 0.5f * x0 * (1.0f + erff(x0 * 0.70710678118654752f));  // exact gelu
        s00 = fmaf(g0, w0, s00); s01 = fmaf(g0, w1w, s01); s02 = fmaf(g0, w2w, s02);
        float x1 = h1[j];
        float g1 = 0.5f * x1 * (1.0f + erff(x1 * 0.70710678118654752f));
        s10 = fmaf(g1, w0, s10); s11 = fmaf(g1, w1w, s11); s12 = fmaf(g1, w2w, s12);
    }
    // reduce across the 4 quarters of this pair (lanes differ in bits 0..1)
    s00 += __shfl_xor_sync(0xffffffffu, s00, 1);
    s01 += __shfl_xor_sync(0xffffffffu, s01, 1);
    s02 += __shfl_xor_sync(0xffffffffu, s02, 1);
    s10 += __shfl_xor_sync(0xffffffffu, s10, 1);
    s11 += __shfl_xor_sync(0xffffffffu, s11, 1);
    s12 += __shfl_xor_sync(0xffffffffu, s12, 1);
    s00 += __shfl_xor_sync(0xffffffffu, s00, 2);
    s01 += __shfl_xor_sync(0xffffffffu, s01, 2);
    s02 += __shfl_xor_sync(0xffffffffu, s02, 2);
    s10 += __shfl_xor_sync(0xffffffffu, s10, 2);
    s11 += __shfl_xor_sync(0xffffffffu, s11, 2);
    s12 += __shfl_xor_sync(0xffffffffu, s12, 2);

    if (qt == 0) {
        #pragma unroll
        for (int t = 0; t < 2; t++) {
            float s0 = (t ? s10 : s00) + b2s[0];
            float s1 = (t ? s11 : s01) + b2s[1];
            float s2 = (t ? s12 : s02) + b2s[2];
            float sx  = fmaxf(s0, 0.0f) + 1.0f;
            float sy  = fmaxf(s1, 0.0f) + 1.0f;
            float rho = 0.99f * tanhf(s2);
            float sxx = sx * sx;
            float syy = sy * sy;
            float sxy = rho * sx * sy;
            float det = sxx * syy - sxy * sxy;   // > 0 always (rho^2 < 0.9801)
            float rdet = 1.0f / det;
            // POSITIVE quadratic form: w'' = -w * log2e
            g_coef4[2 * pair + t] = make_float4( 0.5f * syy * rdet * LOG2E,
                                                -sxy * rdet * LOG2E,
                                                 0.5f * sxx * rdet * LOG2E, 0.f);
        }
    }
}

// ---------------------------------------------------------------------------
// Kernel 2: elementwise mask — EXACT R8 configuration (measured optimum).
// Row-max provably 1.0 -> no reduction. Odds form A = exp2(w'')-1
// (Sterbenz-exact), clamped to the f32 image of clip(p, 1e-6, 1-1e-6).
// r = A*(1-u)*rcp(u);  mask = rcp(1 + r^10).
// Main blocks: only non-crossing float4 vectors (branch-free warps);
// 5193 crossing vectors handled by dedicated tail blocks.
// ---------------------------------------------------------------------------
__device__ __forceinline__ float mask_lane(float uu, float xx, float xy, float yy,
                                           float4 c)
{
    float w = fmaf(c.x, xx, fmaf(c.y, xy, c.z * yy));   // >= 0
    float A = ex2a(w) - 1.0f;
    A = fminf(fmaxf(A, 1.0132800e-06f), 999999.0f);
    float r = A * (1.0f - uu) * rcpa(uu);
    float r2 = r * r;
    float r4 = r2 * r2;
    float r10 = r4 * r4 * r2;
    return rcpa(1.0f + r10);
}

__global__ __launch_bounds__(256, 6) void mask_kernel(
    const float* __restrict__ u,
    const float* __restrict__ dists,
    float* __restrict__ out)
{
    const float2* __restrict__ d2 = (const float2*)dists;
    const unsigned bx = blockIdx.x;

    if (bx < NB_MAIN) {
        const unsigned v = bx * 256u + threadIdx.x;
        if (v >= SLAB4) return;
        const unsigned e0 = v * 4u;

        const unsigned rowg = e0 / 577u;          // 0..6923 (= bhl*577 + i)
        const unsigned j    = e0 - rowg * 577u;
        if (j > 573u) return;                     // crossing vector: tail blocks
        const unsigned i    = rowg % 577u;

        const float2* dp = d2 + (size_t)i * 577u + j;
        const float2 d0 = dp[0], d1 = dp[1], dd2 = dp[2], d3 = dp[3];
        const float xx0 = d0.x*d0.x,   xy0 = d0.x*d0.y,   yy0 = d0.y*d0.y;
        const float xx1 = d1.x*d1.x,   xy1 = d1.x*d1.y,   yy1 = d1.y*d1.y;
        const float xx2 = dd2.x*dd2.x, xy2 = dd2.x*dd2.y, yy2 = dd2.y*dd2.y;
        const float xx3 = d3.x*d3.x,   xy3 = d3.x*d3.y,   yy3 = d3.y*d3.y;

        size_t off = e0;
        unsigned ci = rowg;
        #pragma unroll 2
        for (int b = 0; b < 8; b++) {
            const float4 c  = __ldg(&g_coef4[ci]);
            const float4 u4 = __ldcs((const float4*)(u + off));
            float4 res;
            res.x = mask_lane(u4.x, xx0, xy0, yy0, c);
            res.y = mask_lane(u4.y, xx1, xy1, yy1, c);
            res.z = mask_lane(u4.z, xx2, xy2, yy2, c);
            res.w = mask_lane(u4.w, xx3, xy3, yy3, c);
            __stcs((float4*)(out + off), res);
            off += (size_t)SLAB;
            ci  += NROWS;
        }
    } else {
        // ---- crossing vectors: t -> m (skip m%4==0) -> vector floor(577m/4)
        const unsigned t = (bx - NB_MAIN) * 256u + threadIdx.x;
        if (t >= N_CROSS) return;
        const unsigned m   = t + t / 3u + 1u;     // 1,2,3,5,6,7,9,...
        const unsigned bnd = m * 577u;            // boundary element index
        const unsigned e0  = bnd & ~3u;

        unsigned rowk[4];
        float xxl[4], xyl[4], yyl[4];
        #pragma unroll
        for (int k = 0; k < 4; k++) {
            const unsigned ek = e0 + (unsigned)k;
            const unsigned rg = (ek < bnd) ? (m - 1u) : m;
            rowk[k] = rg;
            const unsigned jk = ek - rg * 577u;
            const unsigned ik = rg % 577u;
            const float2 d = d2[(size_t)ik * 577u + jk];
            xxl[k] = d.x*d.x; xyl[k] = d.x*d.y; yyl[k] = d.y*d.y;
        }

        size_t off = e0;
        for (int b = 0; b < 8; b++) {
            const float4 u4 = __ldcs((const float4*)(u + off));
            const float ul[4] = {u4.x, u4.y, u4.z, u4.w};
            float rl[4];
            const unsigned cb = (unsigned)b * NROWS;
            #pragma unroll
            for (int k = 0; k < 4; k++) {
                const float4 c = __ldg(&g_coef4[cb + rowk[k]]);
                rl[k] = mask_lane(ul[k], xxl[k], xyl[k], yyl[k], c);
            }
            __stcs((float4*)(out + off), make_float4(rl[0], rl[1], rl[2], rl[3]));
            off += (size_t)SLAB;
        }
    }
}

extern "C" void kernel_launch(void* const* d_in, const int* in_sizes, int n_in,
                              void* d_out, int out_size)
{
    const float* query = (const float*)d_in[0];
    const float* W1    = (const float*)d_in[1];
    const float* b1    = (const float*)d_in[2];
    const float* W2    = (const float*)d_in[3];
    const float* b2    = (const float*)d_in[4];
    const float* u     = (const float*)d_in[5];
    const float* dists = (const float*)d_in[6];
    float* out = (float*)d_out;

    mlp_kernel<<<(NPAIR + 63) / 64, 256>>>(query, W1, b1, W2, b2);

    mask_kernel<<<NB_MAIN + NB_CROSS, 256>>>(u, dists, out);
}

// round 13
// speedup vs baseline: 1.4763x; 1.0120x over previous
#include <cuda_runtime.h>
#include <cuda_bf16.h>

#define B_ 8
#define H_ 12
#define N_ 577
#define HD_ 64
#define BH_ (B_*H_)            // 96
#define NTOK (BH_*N_)          // 55392
#define NPAIR (NTOK/2)         // 27696
#define NNU  332929u           // N*N
#define SLAB (12u*NNU)         // one batch slab: 3,995,148 (divisible by 4)
#define SLAB4 (SLAB/4u)        // 998,787
#define NROWS (12u*577u)       // 6924 rows per slab
#define LOG2E 1.4426950408889634f

#define NB_MAIN ((SLAB4 + 255u)/256u)     // 3902
#define N_CROSS 5193u                      // boundaries 577m, m=1..6923, m%4!=0
#define NB_CROSS ((N_CROSS + 255u)/256u)  // 21

// Per-token coefficients, sign-flipped & pre-scaled by log2(e):
// w'' = c.x*dx^2 + c.y*dx*dy + c.z*dy^2  >= 0,  p = exp2(-w'')
__device__ float4 g_coef4[NTOK];

__device__ __forceinline__ float ex2a(float x){ float r; asm("ex2.approx.f32 %0,%1;" : "=f"(r) : "f"(x)); return r; }
__device__ __forceinline__ float rcpa(float x){ float r; asm("rcp.approx.f32 %0,%1;" : "=f"(r) : "f"(x)); return r; }

// Branch-free gelu: 0.5*x*(1+erf(x/sqrt(2))) with A&S 7.1.26 erf (|err|<=1.5e-7).
// No BSSY/BSYNC reconvergence overhead, 2 MUFU. Hidden pre-activations are
// N(0,~0.16^2) so |z|<=~1; min(erf,1) guards the (>9 sigma) tail.
__device__ __forceinline__ float gelu_fast(float x)
{
    float z = fabsf(x) * 0.70710678118654752f;
    float t = rcpa(fmaf(0.3275911f, z, 1.0f));
    float poly = fmaf(fmaf(fmaf(fmaf(1.061405429f, t, -1.453152027f), t,
                          1.421413741f), t, -0.284496736f), t, 0.254829592f) * t;
    float e = ex2a(-z * z * LOG2E);
    float erfz = fminf(fmaf(-poly, e, 1.0f), 1.0f);
    float erfs = copysignf(erfz, x);
    return 0.5f * x * (1.0f + erfs);
}

// Branch-free tanh via ex2 (s clamped: tanh saturated to 1e-9 beyond +-10).
__device__ __forceinline__ float tanh_fast(float s)
{
    s = fminf(fmaxf(s, -10.0f), 10.0f);
    float t2 = ex2a(s * (2.0f * LOG2E));
    return (t2 - 1.0f) * rcpa(t2 + 1.0f);
}

// ---------------------------------------------------------------------------
// Kernel 1: sigma MLP — quarter-split token pairs (R12 structure).
// Each thread: 16 hidden units x 2 consecutive tokens; 4 threads/pair,
// shfl_xor(1),(2) reduction; branch-free transcendentals.
// ---------------------------------------------------------------------------
__global__ __launch_bounds__(256, 4) void mlp_kernel(
    const float* __restrict__ q,
    const float* __restrict__ W1,
    const float* __restrict__ b1,
    const float* __restrict__ W2,
    const float* __restrict__ b2)
{
    __shared__ float4 w1s[64 * 16];   // [k][j4]
    __shared__ float  b1s[64];
    __shared__ float  w2s[64 * 3];
    __shared__ float  b2s[3];

    const int tid = threadIdx.x;
    for (int idx = tid; idx < 1024; idx += 256) w1s[idx] = ((const float4*)W1)[idx];
    if (tid < 64)  b1s[tid] = b1[tid];
    if (tid < 192) w2s[tid] = W2[tid];
    if (tid < 3)   b2s[tid] = b2[tid];
    __syncthreads();

    int pair = blockIdx.x * 64 + (tid >> 2);
    if (pair >= NPAIR) pair = NPAIR - 1;        // duplicate write, same value: benign
    const int qt = tid & 3;                      // hidden-unit quarter

    const float4* q0 = (const float4*)(q + (size_t)(2 * pair) * HD_);
    const float4* q1 = q0 + 16;

    float h0[16], h1[16];
    #pragma unroll
    for (int j = 0; j < 16; j++) { float b = b1s[qt * 16 + j]; h0[j] = b; h1[j] = b; }

    const int jbase = qt * 4;                    // float4 offset into 16-wide row
    #pragma unroll 2
    for (int k4 = 0; k4 < 16; k4++) {
        float4 a0 = q0[k4];
        float4 a1 = q1[k4];
        float c0k[4] = {a0.x, a0.y, a0.z, a0.w};
        float c1k[4] = {a1.x, a1.y, a1.z, a1.w};
        #pragma unroll
        for (int kk = 0; kk < 4; kk++) {
            const float c0 = c0k[kk];
            const float c1 = c1k[kk];
            const int krow = (k4 * 4 + kk) * 16 + jbase;
            #pragma unroll
            for (int j4 = 0; j4 < 4; j4++) {
                float4 w = w1s[krow + j4];
                h0[4*j4+0] = fmaf(c0, w.x, h0[4*j4+0]);
                h0[4*j4+1] = fmaf(c0, w.y, h0[4*j4+1]);
                h0[4*j4+2] = fmaf(c0, w.z, h0[4*j4+2]);
                h0[4*j4+3] = fmaf(c0, w.w, h0[4*j4+3]);
                h1[4*j4+0] = fmaf(c1, w.x, h1[4*j4+0]);
                h1[4*j4+1] = fmaf(c1, w.y, h1[4*j4+1]);
                h1[4*j4+2] = fmaf(c1, w.z, h1[4*j4+2]);
                h1[4*j4+3] = fmaf(c1, w.w, h1[4*j4+3]);
            }
        }
    }

    float s00 = 0.f, s01 = 0.f, s02 = 0.f;
    float s10 = 0.f, s11 = 0.f, s12 = 0.f;
    #pragma unroll
    for (int j = 0; j < 16; j++) {
        const int jg = (qt * 16 + j) * 3;
        const float w0 = w2s[jg+0], w1w = w2s[jg+1], w2w = w2s[jg+2];
        float g0 = gelu_fast(h0[j]);
        s00 = fmaf(g0, w0, s00); s01 = fmaf(g0, w1w, s01); s02 = fmaf(g0, w2w, s02);
        float g1 = gelu_fast(h1[j]);
        s10 = fmaf(g1, w0, s10); s11 = fmaf(g1, w1w, s11); s12 = fmaf(g1, w2w, s12);
    }
    // reduce across the 4 quarters of this pair (lanes differ in bits 0..1)
    s00 += __shfl_xor_sync(0xffffffffu, s00, 1);
    s01 += __shfl_xor_sync(0xffffffffu, s01, 1);
    s02 += __shfl_xor_sync(0xffffffffu, s02, 1);
    s10 += __shfl_xor_sync(0xffffffffu, s10, 1);
    s11 += __shfl_xor_sync(0xffffffffu, s11, 1);
    s12 += __shfl_xor_sync(0xffffffffu, s12, 1);
    s00 += __shfl_xor_sync(0xffffffffu, s00, 2);
    s01 += __shfl_xor_sync(0xffffffffu, s01, 2);
    s02 += __shfl_xor_sync(0xffffffffu, s02, 2);
    s10 += __shfl_xor_sync(0xffffffffu, s10, 2);
    s11 += __shfl_xor_sync(0xffffffffu, s11, 2);
    s12 += __shfl_xor_sync(0xffffffffu, s12, 2);

    if (qt == 0) {
        #pragma unroll
        for (int t = 0; t < 2; t++) {
            float s0 = (t ? s10 : s00) + b2s[0];
            float s1 = (t ? s11 : s01) + b2s[1];
            float s2 = (t ? s12 : s02) + b2s[2];
            float sx  = fmaxf(s0, 0.0f) + 1.0f;
            float sy  = fmaxf(s1, 0.0f) + 1.0f;
            float rho = 0.99f * tanh_fast(s2);
            float sxx = sx * sx;
            float syy = sy * sy;
            float sxy = rho * sx * sy;
            float det = sxx * syy - sxy * sxy;   // > 0 always (rho^2 < 0.9801)
            float rdet = 1.0f / det;
            // POSITIVE quadratic form: w'' = -w * log2e
            g_coef4[2 * pair + t] = make_float4( 0.5f * syy * rdet * LOG2E,
                                                -sxy * rdet * LOG2E,
                                                 0.5f * sxx * rdet * LOG2E, 0.f);
        }
    }
}

// ---------------------------------------------------------------------------
// Kernel 2: elementwise mask — EXACT R8/R12 configuration (measured optimum).
// Row-max provably 1.0 -> no reduction. Odds form A = exp2(w'')-1
// (Sterbenz-exact), clamped to the f32 image of clip(p, 1e-6, 1-1e-6).
// r = A*(1-u)*rcp(u);  mask = rcp(1 + r^10).
// ---------------------------------------------------------------------------
__device__ __forceinline__ float mask_lane(float uu, float xx, float xy, float yy,
                                           float4 c)
{
    float w = fmaf(c.x, xx, fmaf(c.y, xy, c.z * yy));   // >= 0
    float A = ex2a(w) - 1.0f;
    A = fminf(fmaxf(A, 1.0132800e-06f), 999999.0f);
    float r = A * (1.0f - uu) * rcpa(uu);
    float r2 = r * r;
    float r4 = r2 * r2;
    float r10 = r4 * r4 * r2;
    return rcpa(1.0f + r10);
}

__global__ __launch_bounds__(256, 6) void mask_kernel(
    const float* __restrict__ u,
    const float* __restrict__ dists,
    float* __restrict__ out)
{
    const float2* __restrict__ d2 = (const float2*)dists;
    const unsigned bx = blockIdx.x;

    if (bx < NB_MAIN) {
        const unsigned v = bx * 256u + threadIdx.x;
        if (v >= SLAB4) return;
        const unsigned e0 = v * 4u;

        const unsigned rowg = e0 / 577u;          // 0..6923 (= bhl*577 + i)
        const unsigned j    = e0 - rowg * 577u;
        if (j > 573u) return;                     // crossing vector: tail blocks
        const unsigned i    = rowg % 577u;

        const float2* dp = d2 + (size_t)i * 577u + j;
        const float2 d0 = dp[0], d1 = dp[1], dd2 = dp[2], d3 = dp[3];
        const float xx0 = d0.x*d0.x,   xy0 = d0.x*d0.y,   yy0 = d0.y*d0.y;
        const float xx1 = d1.x*d1.x,   xy1 = d1.x*d1.y,   yy1 = d1.y*d1.y;
        const float xx2 = dd2.x*dd2.x, xy2 = dd2.x*dd2.y, yy2 = dd2.y*dd2.y;
        const float xx3 = d3.x*d3.x,   xy3 = d3.x*d3.y,   yy3 = d3.y*d3.y;

        size_t off = e0;
        unsigned ci = rowg;
        #pragma unroll 2
        for (int b = 0; b < 8; b++) {
            const float4 c  = __ldg(&g_coef4[ci]);
            const float4 u4 = __ldcs((const float4*)(u + off));
            float4 res;
            res.x = mask_lane(u4.x, xx0, xy0, yy0, c);
            res.y = mask_lane(u4.y, xx1, xy1, yy1, c);
            res.z = mask_lane(u4.z, xx2, xy2, yy2, c);
            res.w = mask_lane(u4.w, xx3, xy3, yy3, c);
            __stcs((float4*)(out + off), res);
            off += (size_t)SLAB;
            ci  += NROWS;
        }
    } else {
        // ---- crossing vectors: t -> m (skip m%4==0) -> vector floor(577m/4)
        const unsigned t = (bx - NB_MAIN) * 256u + threadIdx.x;
        if (t >= N_CROSS) return;
        const unsigned m   = t + t / 3u + 1u;     // 1,2,3,5,6,7,9,...
        const unsigned bnd = m * 577u;            // boundary element index
        const unsigned e0  = bnd & ~3u;

        unsigned rowk[4];
        float xxl[4], xyl[4], yyl[4];
        #pragma unroll
        for (int k = 0; k < 4; k++) {
            const unsigned ek = e0 + (unsigned)k;
            const unsigned rg = (ek < bnd) ? (m - 1u) : m;
            rowk[k] = rg;
            const unsigned jk = ek - rg * 577u;
            const unsigned ik = rg % 577u;
            const float2 d = d2[(size_t)ik * 577u + jk];
            xxl[k] = d.x*d.x; xyl[k] = d.x*d.y; yyl[k] = d.y*d.y;
        }

        size_t off = e0;
        for (int b = 0; b < 8; b++) {
            const float4 u4 = __ldcs((const float4*)(u + off));
            const float ul[4] = {u4.x, u4.y, u4.z, u4.w};
            float rl[4];
            const unsigned cb = (unsigned)b * NROWS;
            #pragma unroll
            for (int k = 0; k < 4; k++) {
                const float4 c = __ldg(&g_coef4[cb + rowk[k]]);
                rl[k] = mask_lane(ul[k], xxl[k], xyl[k], yyl[k], c);
            }
            __stcs((float4*)(out + off), make_float4(rl[0], rl[1], rl[2], rl[3]));
            off += (size_t)SLAB;
        }
    }
}

extern "C" void kernel_launch(void* const* d_in, const int* in_sizes, int n_in,
                              void* d_out, int out_size)
{
    const float* query = (const float*)d_in[0];
    const float* W1    = (const float*)d_in[1];
    const float* b1    = (const float*)d_in[2];
    const float* W2    = (const float*)d_in[3];
    const float* b2    = (const float*)d_in[4];
    const float* u     = (const float*)d_in[5];
    const float* dists = (const float*)d_in[6];
    float* out = (float*)d_out;

    mlp_kernel<<<(NPAIR + 63) / 64, 256>>>(query, W1, b1, W2, b2);

    mask_kernel<<<NB_MAIN + NB_CROSS, 256>>>(u, dists, out);
}